// round 16
// baseline (speedup 1.0000x reference)
#include <cuda_runtime.h>
#include <math.h>

#define NN     50000
#define EE     800000
#define ETMAX  (EE + NN)
#define INC    128
#define HEADS  3
#define HID    64
#define H1DIM  (HEADS * HID) // 192
#define OUTC   64

#define NEG_SLOPE 0.2f
#define EPSF 1e-16f

#define LRELU(t) (((t) > 0.f) ? (t) : NEG_SLOPE * (t))

// ---------------- scratch (static device globals; no allocations) -------------
__device__ float  g_h1  [(size_t)NN * H1DIM];   // x @ W1
__device__ float  g_out1[(size_t)NN * H1DIM];   // layer1 output (post ELU)
__device__ float  g_h2  [(size_t)NN * OUTC];    // out1 @ W2
__device__ float4 g_s1  [NN];                   // packed (as0,as1,as2,_)
__device__ float4 g_d1  [NN];                   // packed (ad0,ad1,ad2,_)
__device__ float  g_as2 [NN];
__device__ float  g_ad2 [NN];
__device__ int    g_deg   [NN];
__device__ int    g_cursor[NN];
__device__ int    g_off   [NN + 1];
__device__ int    g_elist [ETMAX];

// ---------------- CSR build ---------------------------------------------------
__global__ void k_hist(const int* __restrict__ ei, int* __restrict__ deg,
                       int e_real, int et) {
    int i = blockIdx.x * blockDim.x + threadIdx.x;
    if (i >= et) return;
    int dst = (i < e_real) ? ei[e_real + i] : (i - e_real);
    atomicAdd(&deg[dst], 1);
}

// single-block scan; also zeroes cursor
__global__ void k_scan(const int* __restrict__ deg, int* __restrict__ off,
                       int* __restrict__ cur, int n) {
    __shared__ int part[1024];
    int t = threadIdx.x;
    int chunk = (n + 1023) / 1024;
    int b = t * chunk;
    int s = 0;
    for (int j = 0; j < chunk; j++) { int idx = b + j; if (idx < n) s += deg[idx]; }
    part[t] = s;
    __syncthreads();
    for (int d = 1; d < 1024; d <<= 1) {
        int v = (t >= d) ? part[t - d] : 0;
        __syncthreads();
        part[t] += v;
        __syncthreads();
    }
    int run = (t == 0) ? 0 : part[t - 1];
    for (int j = 0; j < chunk; j++) {
        int idx = b + j;
        if (idx < n) { off[idx] = run; run += deg[idx]; cur[idx] = 0; }
    }
    if (t == 1023) off[n] = part[1023];
}

__global__ void k_bucket(const int* __restrict__ ei, const int* __restrict__ off,
                         int* __restrict__ cur, int* __restrict__ elist,
                         int e_real, int et) {
    int i = blockIdx.x * blockDim.x + threadIdx.x;
    if (i >= et) return;
    int src, dst;
    if (i < e_real) { src = ei[i]; dst = ei[e_real + i]; }
    else            { src = i - e_real; dst = src; }
    int pos = atomicAdd(&cur[dst], 1);
    elist[off[dst] + pos] = src;
}

// ---------------- GEMM1: h1 = x @ W1 with fused per-head logits ---------------
// BN=64 and H1DIM=192 => blockIdx.x IS the head index. Epilogue computes
// row dots with att_src1[h]/att_dst1[h] and writes component h of s1/d1.
__global__ void k_gemm1(const float* __restrict__ A, const float* __restrict__ B,
                        const float* __restrict__ att_s, const float* __restrict__ att_d,
                        float* __restrict__ C, float4* __restrict__ s1,
                        float4* __restrict__ d1, int M) {
    __shared__ float As[16][129];
    __shared__ float Bs[16][68];

    int tid = threadIdx.x;
    int tx = tid & 15, ty = tid >> 4;
    int m0 = blockIdx.y * 128;
    int head = blockIdx.x;
    int n0 = head * 64;

    float acc[8][4];
    #pragma unroll
    for (int i = 0; i < 8; i++)
        #pragma unroll
        for (int j = 0; j < 4; j++) acc[i][j] = 0.0f;

    for (int k0 = 0; k0 < INC; k0 += 16) {
        #pragma unroll
        for (int q = 0; q < 2; q++) {
            int slot = tid + q * 256;
            int row = slot >> 2, kq = slot & 3;
            int gm = m0 + row;
            float4 v = make_float4(0.f, 0.f, 0.f, 0.f);
            if (gm < M) v = *(const float4*)&A[(size_t)gm * INC + k0 + kq * 4];
            As[kq * 4 + 0][row] = v.x;
            As[kq * 4 + 1][row] = v.y;
            As[kq * 4 + 2][row] = v.z;
            As[kq * 4 + 3][row] = v.w;
        }
        {
            int kk = tid >> 4, col4 = (tid & 15) * 4;
            float4 v = *(const float4*)&B[(size_t)(k0 + kk) * H1DIM + n0 + col4];
            Bs[kk][col4 + 0] = v.x; Bs[kk][col4 + 1] = v.y;
            Bs[kk][col4 + 2] = v.z; Bs[kk][col4 + 3] = v.w;
        }
        __syncthreads();

        #pragma unroll
        for (int kk = 0; kk < 16; kk++) {
            float a[8], b[4];
            #pragma unroll
            for (int i = 0; i < 8; i++) a[i] = As[kk][ty * 8 + i];
            #pragma unroll
            for (int j = 0; j < 4; j++) b[j] = Bs[kk][tx * 4 + j];
            #pragma unroll
            for (int i = 0; i < 8; i++)
                #pragma unroll
                for (int j = 0; j < 4; j++) acc[i][j] = fmaf(a[i], b[j], acc[i][j]);
        }
        __syncthreads();
    }

    // att vectors for this thread's 4 columns of this head
    float avs[4], avd[4];
    #pragma unroll
    for (int j = 0; j < 4; j++) {
        avs[j] = att_s[n0 + tx * 4 + j];
        avd[j] = att_d[n0 + tx * 4 + j];
    }

    #pragma unroll
    for (int i = 0; i < 8; i++) {
        int gm = m0 + ty * 8 + i;
        float ps = 0.f, pd = 0.f;
        #pragma unroll
        for (int j = 0; j < 4; j++) {
            ps = fmaf(acc[i][j], avs[j], ps);
            pd = fmaf(acc[i][j], avd[j], pd);
        }
        #pragma unroll
        for (int o = 8; o > 0; o >>= 1) {
            ps += __shfl_down_sync(0xffffffff, ps, o, 16);
            pd += __shfl_down_sync(0xffffffff, pd, o, 16);
        }
        if (gm < M) {
            float4 v = make_float4(acc[i][0], acc[i][1], acc[i][2], acc[i][3]);
            *(float4*)&C[(size_t)gm * H1DIM + n0 + tx * 4] = v;
            if (tx == 0) {
                ((float*)&s1[gm])[head] = ps;
                ((float*)&d1[gm])[head] = pd;
            }
        }
    }
}

// ---------------- GEMM2 (N=64, K=192) with fused att2 logits ------------------
__global__ void k_gemm2(const float* __restrict__ A, const float* __restrict__ B,
                        const float* __restrict__ att_s, const float* __restrict__ att_d,
                        float* __restrict__ C, float* __restrict__ as2,
                        float* __restrict__ ad2, int M) {
    __shared__ float As[16][129];
    __shared__ float Bs[16][68];

    int tid = threadIdx.x;
    int tx = tid & 15, ty = tid >> 4;
    int m0 = blockIdx.y * 128;

    float acc[8][4];
    #pragma unroll
    for (int i = 0; i < 8; i++)
        #pragma unroll
        for (int j = 0; j < 4; j++) acc[i][j] = 0.0f;

    for (int k0 = 0; k0 < H1DIM; k0 += 16) {
        #pragma unroll
        for (int q = 0; q < 2; q++) {
            int slot = tid + q * 256;
            int row = slot >> 2, kq = slot & 3;
            int gm = m0 + row;
            float4 v = make_float4(0.f, 0.f, 0.f, 0.f);
            if (gm < M) v = *(const float4*)&A[(size_t)gm * H1DIM + k0 + kq * 4];
            As[kq * 4 + 0][row] = v.x;
            As[kq * 4 + 1][row] = v.y;
            As[kq * 4 + 2][row] = v.z;
            As[kq * 4 + 3][row] = v.w;
        }
        {
            int kk = tid >> 4, col4 = (tid & 15) * 4;
            float4 v = *(const float4*)&B[(size_t)(k0 + kk) * OUTC + col4];
            Bs[kk][col4 + 0] = v.x; Bs[kk][col4 + 1] = v.y;
            Bs[kk][col4 + 2] = v.z; Bs[kk][col4 + 3] = v.w;
        }
        __syncthreads();

        #pragma unroll
        for (int kk = 0; kk < 16; kk++) {
            float a[8], b[4];
            #pragma unroll
            for (int i = 0; i < 8; i++) a[i] = As[kk][ty * 8 + i];
            #pragma unroll
            for (int j = 0; j < 4; j++) b[j] = Bs[kk][tx * 4 + j];
            #pragma unroll
            for (int i = 0; i < 8; i++)
                #pragma unroll
                for (int j = 0; j < 4; j++) acc[i][j] = fmaf(a[i], b[j], acc[i][j]);
        }
        __syncthreads();
    }

    float avs[4], avd[4];
    #pragma unroll
    for (int j = 0; j < 4; j++) {
        avs[j] = att_s[tx * 4 + j];
        avd[j] = att_d[tx * 4 + j];
    }

    #pragma unroll
    for (int i = 0; i < 8; i++) {
        int gm = m0 + ty * 8 + i;
        float ps = 0.f, pd = 0.f;
        #pragma unroll
        for (int j = 0; j < 4; j++) {
            ps = fmaf(acc[i][j], avs[j], ps);
            pd = fmaf(acc[i][j], avd[j], pd);
        }
        #pragma unroll
        for (int o = 8; o > 0; o >>= 1) {
            ps += __shfl_down_sync(0xffffffff, ps, o, 16);
            pd += __shfl_down_sync(0xffffffff, pd, o, 16);
        }
        if (gm < M) {
            float4 v = make_float4(acc[i][0], acc[i][1], acc[i][2], acc[i][3]);
            *(float4*)&C[(size_t)gm * OUTC + tx * 4] = v;
            if (tx == 0) { as2[gm] = ps; ad2[gm] = pd; }
        }
    }
}

// ---------------- fused GAT layer 1: single-pass online softmax ---------------
__global__ void k_gat1(const int* __restrict__ elist, const int* __restrict__ off,
                       const float4* __restrict__ sp1, const float4* __restrict__ dp1,
                       const float* __restrict__ h1, const float* __restrict__ b1,
                       float* __restrict__ out1, int n) {
    int dst = blockIdx.x * (blockDim.x >> 5) + (threadIdx.x >> 5);
    int lane = threadIdx.x & 31;
    if (dst >= n) return;
    int beg = off[dst], end = off[dst + 1];
    float4 ad = dp1[dst];
    bool is_h0 = (lane < 16);

    float mA = -INFINITY, mB = -INFINITY, sA = 0.f, sB = 0.f;
    float4 acc4 = make_float4(0.f, 0.f, 0.f, 0.f);
    float2 acc2 = make_float2(0.f, 0.f);

    int i = beg;
    for (; i + 4 <= end; i += 4) {
        int e0 = elist[i], e1 = elist[i + 1], e2 = elist[i + 2], e3 = elist[i + 3];
        float4 q0 = sp1[e0], q1 = sp1[e1], q2 = sp1[e2], q3 = sp1[e3];
        const float* r0 = h1 + (size_t)e0 * H1DIM;
        const float* r1 = h1 + (size_t)e1 * H1DIM;
        const float* r2 = h1 + (size_t)e2 * H1DIM;
        const float* r3 = h1 + (size_t)e3 * H1DIM;
        float4 x0 = ((const float4*)r0)[lane];
        float4 x1 = ((const float4*)r1)[lane];
        float4 x2 = ((const float4*)r2)[lane];
        float4 x3 = ((const float4*)r3)[lane];
        float2 y0 = *(const float2*)(r0 + 128 + 2 * lane);
        float2 y1 = *(const float2*)(r1 + 128 + 2 * lane);
        float2 y2 = *(const float2*)(r2 + 128 + 2 * lane);
        float2 y3 = *(const float2*)(r3 + 128 + 2 * lane);

        float vA0 = LRELU(is_h0 ? (q0.x + ad.x) : (q0.y + ad.y));
        float vA1 = LRELU(is_h0 ? (q1.x + ad.x) : (q1.y + ad.y));
        float vA2 = LRELU(is_h0 ? (q2.x + ad.x) : (q2.y + ad.y));
        float vA3 = LRELU(is_h0 ? (q3.x + ad.x) : (q3.y + ad.y));
        float vB0 = LRELU(q0.z + ad.z);
        float vB1 = LRELU(q1.z + ad.z);
        float vB2 = LRELU(q2.z + ad.z);
        float vB3 = LRELU(q3.z + ad.z);

        float bmA = fmaxf(fmaxf(vA0, vA1), fmaxf(vA2, vA3));
        if (bmA > mA) {
            float sc = __expf(mA - bmA);
            sA *= sc; acc4.x *= sc; acc4.y *= sc; acc4.z *= sc; acc4.w *= sc;
            mA = bmA;
        }
        float bmB = fmaxf(fmaxf(vB0, vB1), fmaxf(vB2, vB3));
        if (bmB > mB) {
            float sc = __expf(mB - bmB);
            sB *= sc; acc2.x *= sc; acc2.y *= sc;
            mB = bmB;
        }
        float pA0 = __expf(vA0 - mA), pA1 = __expf(vA1 - mA);
        float pA2 = __expf(vA2 - mA), pA3 = __expf(vA3 - mA);
        float pB0 = __expf(vB0 - mB), pB1 = __expf(vB1 - mB);
        float pB2 = __expf(vB2 - mB), pB3 = __expf(vB3 - mB);
        sA += (pA0 + pA1) + (pA2 + pA3);
        sB += (pB0 + pB1) + (pB2 + pB3);
        acc4.x = fmaf(x0.x, pA0, acc4.x); acc4.y = fmaf(x0.y, pA0, acc4.y);
        acc4.z = fmaf(x0.z, pA0, acc4.z); acc4.w = fmaf(x0.w, pA0, acc4.w);
        acc4.x = fmaf(x1.x, pA1, acc4.x); acc4.y = fmaf(x1.y, pA1, acc4.y);
        acc4.z = fmaf(x1.z, pA1, acc4.z); acc4.w = fmaf(x1.w, pA1, acc4.w);
        acc4.x = fmaf(x2.x, pA2, acc4.x); acc4.y = fmaf(x2.y, pA2, acc4.y);
        acc4.z = fmaf(x2.z, pA2, acc4.z); acc4.w = fmaf(x2.w, pA2, acc4.w);
        acc4.x = fmaf(x3.x, pA3, acc4.x); acc4.y = fmaf(x3.y, pA3, acc4.y);
        acc4.z = fmaf(x3.z, pA3, acc4.z); acc4.w = fmaf(x3.w, pA3, acc4.w);
        acc2.x = fmaf(y0.x, pB0, acc2.x); acc2.y = fmaf(y0.y, pB0, acc2.y);
        acc2.x = fmaf(y1.x, pB1, acc2.x); acc2.y = fmaf(y1.y, pB1, acc2.y);
        acc2.x = fmaf(y2.x, pB2, acc2.x); acc2.y = fmaf(y2.y, pB2, acc2.y);
        acc2.x = fmaf(y3.x, pB3, acc2.x); acc2.y = fmaf(y3.y, pB3, acc2.y);
    }
    for (; i < end; i++) {
        int e0 = elist[i];
        float4 q0 = sp1[e0];
        const float* r0 = h1 + (size_t)e0 * H1DIM;
        float4 x0 = ((const float4*)r0)[lane];
        float2 y0 = *(const float2*)(r0 + 128 + 2 * lane);
        float vA0 = LRELU(is_h0 ? (q0.x + ad.x) : (q0.y + ad.y));
        float vB0 = LRELU(q0.z + ad.z);
        if (vA0 > mA) {
            float sc = __expf(mA - vA0);
            sA *= sc; acc4.x *= sc; acc4.y *= sc; acc4.z *= sc; acc4.w *= sc;
            mA = vA0;
        }
        if (vB0 > mB) {
            float sc = __expf(mB - vB0);
            sB *= sc; acc2.x *= sc; acc2.y *= sc;
            mB = vB0;
        }
        float pA0 = __expf(vA0 - mA);
        float pB0 = __expf(vB0 - mB);
        sA += pA0; sB += pB0;
        acc4.x = fmaf(x0.x, pA0, acc4.x); acc4.y = fmaf(x0.y, pA0, acc4.y);
        acc4.z = fmaf(x0.z, pA0, acc4.z); acc4.w = fmaf(x0.w, pA0, acc4.w);
        acc2.x = fmaf(y0.x, pB0, acc2.x); acc2.y = fmaf(y0.y, pB0, acc2.y);
    }

    float invA = 1.0f / (sA + EPSF);
    float invB = 1.0f / (sB + EPSF);
    float* op = out1 + (size_t)dst * H1DIM;
    float4 bb4 = ((const float4*)b1)[lane];
    float2 bb2 = *(const float2*)(b1 + 128 + 2 * lane);
    float4 o4; float2 o2; float t;
    t = fmaf(acc4.x, invA, bb4.x); o4.x = (t > 0.f) ? t : expm1f(t);
    t = fmaf(acc4.y, invA, bb4.y); o4.y = (t > 0.f) ? t : expm1f(t);
    t = fmaf(acc4.z, invA, bb4.z); o4.z = (t > 0.f) ? t : expm1f(t);
    t = fmaf(acc4.w, invA, bb4.w); o4.w = (t > 0.f) ? t : expm1f(t);
    t = fmaf(acc2.x, invB, bb2.x); o2.x = (t > 0.f) ? t : expm1f(t);
    t = fmaf(acc2.y, invB, bb2.y); o2.y = (t > 0.f) ? t : expm1f(t);
    ((float4*)op)[lane] = o4;
    *(float2*)(op + 128 + 2 * lane) = o2;
}

// ---------------- fused GAT layer 2: single-pass online softmax ---------------
__global__ void k_gat2(const int* __restrict__ elist, const int* __restrict__ off,
                       const float* __restrict__ as2, const float* __restrict__ ad2,
                       const float* __restrict__ h2, const float* __restrict__ b2,
                       float* __restrict__ out, int n) {
    int dst = blockIdx.x * (blockDim.x >> 5) + (threadIdx.x >> 5);
    int lane = threadIdx.x & 31;
    if (dst >= n) return;
    int beg = off[dst], end = off[dst + 1];
    float ad = ad2[dst];

    float m = -INFINITY, s = 0.f;
    float2 acc = make_float2(0.f, 0.f);

    int i = beg;
    for (; i + 4 <= end; i += 4) {
        int e0 = elist[i], e1 = elist[i + 1], e2 = elist[i + 2], e3 = elist[i + 3];
        float a0 = as2[e0], a1 = as2[e1], a2 = as2[e2], a3 = as2[e3];
        float2 y0 = *(const float2*)(h2 + (size_t)e0 * OUTC + 2 * lane);
        float2 y1 = *(const float2*)(h2 + (size_t)e1 * OUTC + 2 * lane);
        float2 y2 = *(const float2*)(h2 + (size_t)e2 * OUTC + 2 * lane);
        float2 y3 = *(const float2*)(h2 + (size_t)e3 * OUTC + 2 * lane);
        float v0 = LRELU(a0 + ad), v1 = LRELU(a1 + ad);
        float v2 = LRELU(a2 + ad), v3 = LRELU(a3 + ad);
        float bm = fmaxf(fmaxf(v0, v1), fmaxf(v2, v3));
        if (bm > m) {
            float sc = __expf(m - bm);
            s *= sc; acc.x *= sc; acc.y *= sc;
            m = bm;
        }
        float p0 = __expf(v0 - m), p1 = __expf(v1 - m);
        float p2 = __expf(v2 - m), p3 = __expf(v3 - m);
        s += (p0 + p1) + (p2 + p3);
        acc.x = fmaf(y0.x, p0, acc.x); acc.y = fmaf(y0.y, p0, acc.y);
        acc.x = fmaf(y1.x, p1, acc.x); acc.y = fmaf(y1.y, p1, acc.y);
        acc.x = fmaf(y2.x, p2, acc.x); acc.y = fmaf(y2.y, p2, acc.y);
        acc.x = fmaf(y3.x, p3, acc.x); acc.y = fmaf(y3.y, p3, acc.y);
    }
    for (; i < end; i++) {
        int e0 = elist[i];
        float a0 = as2[e0];
        float2 y0 = *(const float2*)(h2 + (size_t)e0 * OUTC + 2 * lane);
        float v0 = LRELU(a0 + ad);
        if (v0 > m) {
            float sc = __expf(m - v0);
            s *= sc; acc.x *= sc; acc.y *= sc;
            m = v0;
        }
        float p0 = __expf(v0 - m);
        s += p0;
        acc.x = fmaf(y0.x, p0, acc.x); acc.y = fmaf(y0.y, p0, acc.y);
    }

    float inv = 1.0f / (s + EPSF);
    float2 bb = *(const float2*)(b2 + 2 * lane);
    float2 o;
    o.x = fmaf(acc.x, inv, bb.x);
    o.y = fmaf(acc.y, inv, bb.y);
    *(float2*)(out + (size_t)dst * OUTC + 2 * lane) = o;
}

// ---------------- launcher ----------------
extern "C" void kernel_launch(void* const* d_in, const int* in_sizes, int n_in,
                              void* d_out, int out_size) {
    float *p_h1, *p_out1, *p_h2, *p_as2, *p_ad2;
    float4 *p_s1, *p_d1;
    int *p_deg, *p_cur, *p_off, *p_elist;
    cudaGetSymbolAddress((void**)&p_h1,    g_h1);
    cudaGetSymbolAddress((void**)&p_out1,  g_out1);
    cudaGetSymbolAddress((void**)&p_h2,    g_h2);
    cudaGetSymbolAddress((void**)&p_s1,    g_s1);
    cudaGetSymbolAddress((void**)&p_d1,    g_d1);
    cudaGetSymbolAddress((void**)&p_as2,   g_as2);
    cudaGetSymbolAddress((void**)&p_ad2,   g_ad2);
    cudaGetSymbolAddress((void**)&p_deg,   g_deg);
    cudaGetSymbolAddress((void**)&p_cur,   g_cursor);
    cudaGetSymbolAddress((void**)&p_off,   g_off);
    cudaGetSymbolAddress((void**)&p_elist, g_elist);

    const float* x = nullptr; const int* ei = nullptr;
    const float* W1 = nullptr; const float* W2 = nullptr;
    const float* s192[3] = {nullptr, nullptr, nullptr}; int n192 = 0;
    const float* s64 [3] = {nullptr, nullptr, nullptr}; int n64  = 0;
    for (int i = 0; i < n_in; i++) {
        int sz = in_sizes[i];
        if      (sz == NN * INC)        x  = (const float*)d_in[i];
        else if (sz == 2 * EE)          ei = (const int*)  d_in[i];
        else if (sz == INC * H1DIM)     W1 = (const float*)d_in[i];
        else if (sz == H1DIM * OUTC)    W2 = (const float*)d_in[i];
        else if (sz == H1DIM && n192 < 3) s192[n192++] = (const float*)d_in[i];
        else if (sz == OUTC  && n64  < 3) s64 [n64++]  = (const float*)d_in[i];
    }
    const float* att_src1 = s192[0]; const float* att_dst1 = s192[1]; const float* b1 = s192[2];
    const float* att_src2 = s64[0];  const float* att_dst2 = s64[1];  const float* b2 = s64[2];

    float* out = (float*)d_out;
    int n  = NN;
    int e  = EE;
    int et = e + n;

    // Fork: CSR build on side stream, layer-1 GEMM (with fused logits) on main.
    static cudaStream_t s2 = nullptr;
    static cudaEvent_t evFork = nullptr, evJoin = nullptr;
    if (!s2) {
        cudaStreamCreateWithFlags(&s2, cudaStreamNonBlocking);
        cudaEventCreateWithFlags(&evFork, cudaEventDisableTiming);
        cudaEventCreateWithFlags(&evJoin, cudaEventDisableTiming);
    }

    cudaEventRecord(evFork, 0);
    cudaStreamWaitEvent(s2, evFork, 0);

    // side stream: CSR
    cudaMemsetAsync(p_deg, 0, n * sizeof(int), s2);
    k_hist  <<<(et + 511) / 512, 512, 0, s2>>>(ei, p_deg, e, et);
    k_scan  <<<1, 1024, 0, s2>>>(p_deg, p_off, p_cur, n);
    k_bucket<<<(et + 511) / 512, 512, 0, s2>>>(ei, p_off, p_cur, p_elist, e, et);
    cudaEventRecord(evJoin, s2);

    // main stream: GEMM1 with fused per-head logits (replaces wvec+logits+gemm)
    {
        dim3 grid(HEADS, (n + 127) / 128);
        k_gemm1<<<grid, 256>>>(x, W1, att_src1, att_dst1, p_h1, p_s1, p_d1, n);
    }

    // join: gat1 needs both CSR and h1/logits
    cudaStreamWaitEvent(0, evJoin, 0);
    k_gat1<<<(n + 15) / 16, 512>>>(p_elist, p_off, p_s1, p_d1, p_h1, b1, p_out1, n);

    // layer 2
    {
        dim3 grid(1, (n + 127) / 128);
        k_gemm2<<<grid, 256>>>(p_out1, W2, att_src2, att_dst2, p_h2, p_as2, p_ad2, n);
    }
    k_gat2<<<(n + 15) / 16, 512>>>(p_elist, p_off, p_as2, p_ad2, p_h2, b2, out, n);
}